// round 8
// baseline (speedup 1.0000x reference)
#include <cuda_runtime.h>

// VolumeRotation: B=8, C=16, S=64 — smem-tiled trilinear gather, round 7.
// Tile 16x16x8 per block, window 26(z)x26(y) rows x 32 floats = 86528 B,
// SINGLE buffer, 512 threads, __launch_bounds__(512,2) => 2 blocks/SM so the
// two blocks hide each other's cp.async staging latency.

#define SB 64
#define CB 16
#define S3 (SB*SB*SB)
#define TX 16
#define TY 16
#define TZ 8
#define NTHR 512
#define SPT 4                    // 2048 voxels / 512 threads
#define WWY 26                   // y,z window cells
#define NROWS (WWY*WWY)          // 676
#define WIN_BYTES (NROWS*128)    // 86528
#define NQ (NROWS*7)             // 4732 staged quads (28 floats/row)
#define SLOTS 10                 // ceil(4732/512); slots 0..8 full, slot 9: tid<124

__device__ __forceinline__ void sample_pos(
    float r00, float r01, float r02,
    float r10, float r11, float r12,
    float r20, float r21, float r22,
    int x, int y, int z,
    float& fx, float& fy, float& fz)
{
    const float sc = 2.0f / 63.0f;
    float bx = fmaf((float)x, sc, -1.0f);
    float by = fmaf((float)y, sc, -1.0f);
    float bz = fmaf((float)z, sc, -1.0f);
    float gx = fmaf(r00, bx, fmaf(r10, by, r20 * bz));
    float gy = fmaf(r01, bx, fmaf(r11, by, r21 * bz));
    float gz = fmaf(r02, bx, fmaf(r12, by, r22 * bz));
    fx = fmaf(gx, 32.0f, 31.5f);
    fy = fmaf(gy, 32.0f, 31.5f);
    fz = fmaf(gz, 32.0f, 31.5f);
}

__global__ __launch_bounds__(NTHR, 2)
void volrot_kernel(const float* __restrict__ vol,
                   const float* __restrict__ rot,
                   float* __restrict__ out)
{
    extern __shared__ float smemf[];
    const char* wb = (const char*)smemf;
    unsigned su = (unsigned)__cvta_generic_to_shared(smemf);

    int tid = threadIdx.x;
    int blk = blockIdx.x;
    int b = blk >> 7;                 // 128 tiles per batch
    int t = blk & 127;
    int oz = (t >> 4) * TZ;           // 8 z-tiles
    int oy = ((t >> 2) & 3) * TY;     // 4 y-tiles
    int ox = (t & 3) * TX;            // 4 x-tiles

    const float* R = rot + b * 9;
    float r00 = __ldg(R+0), r01 = __ldg(R+1), r02 = __ldg(R+2);
    float r10 = __ldg(R+3), r11 = __ldg(R+4), r12 = __ldg(R+5);
    float r20 = __ldg(R+6), r21 = __ldg(R+7), r22 = __ldg(R+8);

    // window base: min over 8 tile corners (affine => extremes at corners)
    float mnx = 1e30f, mny = 1e30f, mnz = 1e30f;
    #pragma unroll
    for (int k = 0; k < 8; k++) {
        int cx = ox + ((k & 1) ? TX - 1 : 0);
        int cy = oy + ((k & 2) ? TY - 1 : 0);
        int cz = oz + ((k & 4) ? TZ - 1 : 0);
        float fx, fy, fz;
        sample_pos(r00,r01,r02,r10,r11,r12,r20,r21,r22, cx, cy, cz, fx, fy, fz);
        mnx = fminf(mnx, fx); mny = fminf(mny, fy); mnz = fminf(mnz, fz);
    }
    int bax = ((int)floorf(mnx)) & ~3;
    int bay = (int)floorf(mny);
    int baz = (int)floorf(mnz);

    // ---- staging slots (channel-invariant): quad i = tid + j*512
    unsigned goff[SLOTS], sidx[SLOTS];
    unsigned szmask = 0;
    #pragma unroll
    for (int j = 0; j < SLOTS; j++) {
        int i = tid + j * NTHR;
        int ii = (i < NQ) ? i : 0;
        int rowid = ii / 7;
        int xq = ii - rowid * 7;
        int wz = rowid / WWY;
        int wy = rowid - wz * WWY;
        int gx = bax + (xq << 2);
        int gy = bay + wy;
        int gz = baz + wz;
        bool ok = ((unsigned)gx <= (unsigned)(SB - 4)) &
                  ((unsigned)gy < (unsigned)SB) &
                  ((unsigned)gz < (unsigned)SB);
        goff[j] = ok ? (unsigned)((((gz * SB) + gy) * SB + gx) * 4) : 0u;
        if (ok) szmask |= (1u << j);
        sidx[j] = (unsigned)(rowid * 128 + ((xq ^ (rowid & 7)) << 4));
    }

    // ---- per-sample precompute (channel-invariant, packed)
    unsigned rpk[2];     // 4 rowids, 16 bits each
    unsigned capk[2];    // 4 (ca0,ca1) byte pairs
    float ex0[SPT], ex1[SPT], wp0[SPT], wp1[SPT], wp2[SPT], wp3[SPT];
    unsigned obyte0 = 0;
    rpk[0] = rpk[1] = capk[0] = capk[1] = 0;

    #pragma unroll
    for (int s = 0; s < SPT; s++) {
        int v = tid + s * NTHR;
        int lx = v & 15, ly = (v >> 4) & 15, lz = v >> 8;   // lz 0..7
        int x = ox + lx, y = oy + ly, z = oz + lz;
        float fx, fy, fz;
        sample_pos(r00,r01,r02,r10,r11,r12,r20,r21,r22, x, y, z, fx, fy, fz);
        float x0f = floorf(fx), y0f = floorf(fy), z0f = floorf(fz);
        float txf = fx - x0f, tyf = fy - y0f, tzf = fz - z0f;
        int x0 = (int)x0f, y0 = (int)y0f, z0 = (int)z0f;

        ex0[s] = ((unsigned)x0       < (unsigned)SB) ? (1.0f - txf) : 0.0f;
        ex1[s] = ((unsigned)(x0 + 1) < (unsigned)SB) ? txf          : 0.0f;
        bool vy0 = (unsigned)y0       < (unsigned)SB;
        bool vy1 = (unsigned)(y0 + 1) < (unsigned)SB;
        bool vz0 = (unsigned)z0       < (unsigned)SB;
        bool vz1 = (unsigned)(z0 + 1) < (unsigned)SB;
        wp0[s] = (vy0 && vz0) ? (1.0f - tyf) * (1.0f - tzf) : 0.0f;
        wp1[s] = (vy1 && vz0) ? tyf * (1.0f - tzf)          : 0.0f;
        wp2[s] = (vy0 && vz1) ? (1.0f - tyf) * tzf          : 0.0f;
        wp3[s] = (vy1 && vz1) ? tyf * tzf                   : 0.0f;

        int wx0 = min(max(x0 - bax, 0), 26);
        int wy0 = min(max(y0 - bay, 0), WWY - 2);
        int wz0 = min(max(z0 - baz, 0), WWY - 2);
        unsigned rowid = (unsigned)(wz0 * WWY + wy0);       // <= 648
        rpk[s >> 1] |= rowid << ((s & 1) * 16);
        int xa = wx0, xb = wx0 + 1;
        unsigned ca0 = (unsigned)(((xa >> 2) << 4) | ((xa & 3) << 2));
        unsigned ca1 = (unsigned)(((xb >> 2) << 4) | ((xb & 3) << 2));
        capk[s >> 1] |= (ca0 | (ca1 << 8)) << ((s & 1) * 16);
        if (s == 0) obyte0 = (unsigned)((((z * SB) + y) * SB + x) * 4);
    }

    const char* srcb = (const char*)vol + (size_t)b * CB * S3 * 4;
    char*       dstb = (char*)out       + (size_t)b * CB * S3 * 4;

    #pragma unroll 1
    for (int c = 0; c < CB; c++) {
        __syncthreads();   // previous channel's gather done reading the buffer

        // stage channel c
        const char* g = srcb + (size_t)c * S3 * 4;
        #pragma unroll
        for (int j = 0; j < SLOTS - 1; j++) {
            unsigned sz = ((szmask >> j) & 1u) << 4;
            asm volatile("cp.async.cg.shared.global [%0], [%1], 16, %2;"
                :: "r"(su + sidx[j]), "l"(g + goff[j]), "r"(sz) : "memory");
        }
        if (tid < NQ - (SLOTS - 1) * NTHR) {
            unsigned sz = ((szmask >> (SLOTS - 1)) & 1u) << 4;
            asm volatile("cp.async.cg.shared.global [%0], [%1], 16, %2;"
                :: "r"(su + sidx[SLOTS - 1]), "l"(g + goff[SLOTS - 1]), "r"(sz)
                : "memory");
        }
        asm volatile("cp.async.commit_group;" ::: "memory");

        // compute the 32 smem byte addresses while the fill is in flight
        unsigned adr[SPT][8];
        #pragma unroll
        for (int s = 0; s < SPT; s++) {
            unsigned rowid = (rpk[s >> 1] >> ((s & 1) * 16)) & 0xFFFFu;
            unsigned cap   = (capk[s >> 1] >> ((s & 1) * 16)) & 0xFFFFu;
            unsigned ca0 = cap & 0xFFu;
            unsigned ca1 = (cap >> 8) & 0xFFu;
            const unsigned dj[4] = {0, 1, WWY, WWY + 1};
            #pragma unroll
            for (int r = 0; r < 4; r++) {
                unsigned rr = rowid + dj[r];
                unsigned rk = rr * 128 + ((rr & 7) << 4);
                adr[s][2*r]   = rk ^ ca0;
                adr[s][2*r+1] = rk ^ ca1;
            }
        }

        asm volatile("cp.async.wait_group 0;" ::: "memory");
        __syncthreads();   // staged data visible to all warps

        char* dc = dstb + (size_t)c * S3 * 4 + obyte0;
        #pragma unroll
        for (int s = 0; s < SPT; s++) {
            float v00 = *(const float*)(wb + adr[s][0]);
            float v01 = *(const float*)(wb + adr[s][1]);
            float v10 = *(const float*)(wb + adr[s][2]);
            float v11 = *(const float*)(wb + adr[s][3]);
            float v20 = *(const float*)(wb + adr[s][4]);
            float v21 = *(const float*)(wb + adr[s][5]);
            float v30 = *(const float*)(wb + adr[s][6]);
            float v31 = *(const float*)(wb + adr[s][7]);
            float e0 = ex0[s], e1 = ex1[s];
            float s0 = fmaf(e0, v00, e1 * v01);
            float s1 = fmaf(e0, v10, e1 * v11);
            float s2 = fmaf(e0, v20, e1 * v21);
            float s3 = fmaf(e0, v30, e1 * v31);
            float acc = wp0[s] * s0;
            acc = fmaf(wp1[s], s1, acc);
            acc = fmaf(wp2[s], s2, acc);
            acc = fmaf(wp3[s], s3, acc);
            *(float*)(dc + (unsigned)(s * 32768)) = acc;   // lz step 2 per s
        }
    }
}

extern "C" void kernel_launch(void* const* d_in, const int* in_sizes, int n_in,
                              void* d_out, int out_size)
{
    const float* vol = (const float*)d_in[0];   // [8,16,64,64,64] f32
    const float* rot = (const float*)d_in[1];   // [8,3,3] f32
    float* out = (float*)d_out;

    cudaFuncSetAttribute(volrot_kernel,
                         cudaFuncAttributeMaxDynamicSharedMemorySize, WIN_BYTES);

    volrot_kernel<<<8 * 128, NTHR, WIN_BYTES>>>(vol, rot, out);
}

// round 9
// speedup vs baseline: 1.4106x; 1.4106x over previous
#include <cuda_runtime.h>

// VolumeRotation: B=8, C=16, S=64 — smem-tiled trilinear gather, round 8.
// 16x16x16 tile, window 29x29 rows x 32 floats (107648 B), double-buffered
// cp.async staging with wait_group-1 pipelining, extent-culled staging masks,
// and register budget kept under 64 (no spills): only weights + packed
// rowid/ca cached; all other addressing recomputed per channel.

#define SB 64
#define CB 16
#define S3 (SB*SB*SB)
#define TT 16
#define NTHR 1024
#define SPT 4                    // 4096 voxels / 1024 threads
#define WWN 29                   // y,z window cells
#define NROWS (WWN*WWN)          // 841
#define WIN_BYTES (NROWS*128)    // 107648
#define SMEM_BYTES (2*WIN_BYTES) // 215296
#define SLOTS 7                  // ceil(841*8 / 1024) staging quads per thread

__device__ __forceinline__ void sample_pos(
    float r00, float r01, float r02,
    float r10, float r11, float r12,
    float r20, float r21, float r22,
    int x, int y, int z,
    float& fx, float& fy, float& fz)
{
    const float sc = 2.0f / 63.0f;
    float bx = fmaf((float)x, sc, -1.0f);
    float by = fmaf((float)y, sc, -1.0f);
    float bz = fmaf((float)z, sc, -1.0f);
    float gx = fmaf(r00, bx, fmaf(r10, by, r20 * bz));
    float gy = fmaf(r01, bx, fmaf(r11, by, r21 * bz));
    float gz = fmaf(r02, bx, fmaf(r12, by, r22 * bz));
    fx = fmaf(gx, 32.0f, 31.5f);
    fy = fmaf(gy, 32.0f, 31.5f);
    fz = fmaf(gz, 32.0f, 31.5f);
}

__global__ __launch_bounds__(NTHR, 1)
void volrot_kernel(const float* __restrict__ vol,
                   const float* __restrict__ rot,
                   float* __restrict__ out)
{
    extern __shared__ float smemf[];
    const char* wbase = (const char*)smemf;
    unsigned su = (unsigned)__cvta_generic_to_shared(smemf);

    int tid = threadIdx.x;
    int blk = blockIdx.x;
    int b = blk >> 6;                 // 64 tiles per batch
    int t = blk & 63;
    int oz = (t >> 4) * TT;
    int oy = ((t >> 2) & 3) * TT;
    int ox = (t & 3) * TT;

    const float* R = rot + b * 9;
    float r00 = __ldg(R+0), r01 = __ldg(R+1), r02 = __ldg(R+2);
    float r10 = __ldg(R+3), r11 = __ldg(R+4), r12 = __ldg(R+5);
    float r20 = __ldg(R+6), r21 = __ldg(R+7), r22 = __ldg(R+8);

    // min/max sample coords over the 8 tile corners (affine => hull)
    float mnx = 1e30f, mny = 1e30f, mnz = 1e30f;
    float mxx = -1e30f, mxy = -1e30f, mxz = -1e30f;
    #pragma unroll
    for (int k = 0; k < 8; k++) {
        int cx = ox + ((k & 1) ? TT - 1 : 0);
        int cy = oy + ((k & 2) ? TT - 1 : 0);
        int cz = oz + ((k & 4) ? TT - 1 : 0);
        float fx, fy, fz;
        sample_pos(r00,r01,r02,r10,r11,r12,r20,r21,r22, cx, cy, cz, fx, fy, fz);
        mnx = fminf(mnx, fx); mny = fminf(mny, fy); mnz = fminf(mnz, fz);
        mxx = fmaxf(mxx, fx); mxy = fmaxf(mxy, fy); mxz = fmaxf(mxz, fz);
    }
    int bax = ((int)floorf(mnx)) & ~3;
    int bay = (int)floorf(mny);
    int baz = (int)floorf(mnz);
    int exMax = ((int)floorf(mxx)) + 1 - bax;    // max needed window x index
    int eyMax = ((int)floorf(mxy)) + 1 - bay;
    int ezMax = ((int)floorf(mxz)) + 1 - baz;

    // ---- staging masks (channel-invariant): quad i = tid + j*1024
    int xq = tid & 7;                 // quad within row
    int r0 = tid >> 3;                // row 0..127 (+128 per slot)
    int gxq = bax + (xq << 2);
    unsigned need = 0, inb = 0;
    #pragma unroll
    for (int j = 0; j < SLOTS; j++) {
        int rowid = r0 + j * 128;
        if (rowid < NROWS) {
            int wz = rowid / WWN;
            int wy = rowid - wz * WWN;
            bool nd = ((xq << 2) <= exMax) & (wy <= eyMax) & (wz <= ezMax);
            int gy = bay + wy, gz = baz + wz;
            bool ok = ((unsigned)gxq <= (unsigned)(SB - 4)) &
                      ((unsigned)gy < (unsigned)SB) &
                      ((unsigned)gz < (unsigned)SB);
            if (nd) need |= (1u << j);
            if (ok) inb  |= (1u << j);
        }
    }
    unsigned sidx0 = (unsigned)(r0 * 128 + ((xq ^ (r0 & 7)) << 4));

    // ---- per-sample channel-invariant state (packed small)
    unsigned rpk[2], capk[2];
    float ex0[SPT], ex1[SPT], wp0[SPT], wp1[SPT], wp2[SPT], wp3[SPT];
    unsigned obyte0 = 0;
    rpk[0] = rpk[1] = capk[0] = capk[1] = 0;

    #pragma unroll
    for (int s = 0; s < SPT; s++) {
        int v = tid + s * NTHR;
        int lx = v & 15, ly = (v >> 4) & 15, lz = v >> 8;   // lz 0..15
        int x = ox + lx, y = oy + ly, z = oz + lz;
        float fx, fy, fz;
        sample_pos(r00,r01,r02,r10,r11,r12,r20,r21,r22, x, y, z, fx, fy, fz);
        float x0f = floorf(fx), y0f = floorf(fy), z0f = floorf(fz);
        float txf = fx - x0f, tyf = fy - y0f, tzf = fz - z0f;
        int x0 = (int)x0f, y0 = (int)y0f, z0 = (int)z0f;

        ex0[s] = ((unsigned)x0       < (unsigned)SB) ? (1.0f - txf) : 0.0f;
        ex1[s] = ((unsigned)(x0 + 1) < (unsigned)SB) ? txf          : 0.0f;
        bool vy0 = (unsigned)y0       < (unsigned)SB;
        bool vy1 = (unsigned)(y0 + 1) < (unsigned)SB;
        bool vz0 = (unsigned)z0       < (unsigned)SB;
        bool vz1 = (unsigned)(z0 + 1) < (unsigned)SB;
        wp0[s] = (vy0 && vz0) ? (1.0f - tyf) * (1.0f - tzf) : 0.0f;
        wp1[s] = (vy1 && vz0) ? tyf * (1.0f - tzf)          : 0.0f;
        wp2[s] = (vy0 && vz1) ? (1.0f - tyf) * tzf          : 0.0f;
        wp3[s] = (vy1 && vz1) ? tyf * tzf                   : 0.0f;

        int wx0 = min(max(x0 - bax, 0), 30);
        int wy0 = min(max(y0 - bay, 0), WWN - 2);
        int wz0 = min(max(z0 - baz, 0), WWN - 2);
        unsigned rowid = (unsigned)(wz0 * WWN + wy0);       // <= 783
        rpk[s >> 1] |= rowid << ((s & 1) * 16);
        int xa = wx0, xb = wx0 + 1;
        unsigned ca0 = (unsigned)(((xa >> 2) << 4) | ((xa & 3) << 2));
        unsigned ca1 = (unsigned)(((xb >> 2) << 4) | ((xb & 3) << 2));
        capk[s >> 1] |= (ca0 | (ca1 << 8)) << ((s & 1) * 16);
        if (s == 0) obyte0 = (unsigned)((((z * SB) + y) * SB + x) * 4);
    }

    const char* srcb = (const char*)vol + (size_t)b * CB * S3 * 4;
    char*       dstb = (char*)out       + (size_t)b * CB * S3 * 4;

    // ---- staging fill: recompute goff per call (keeps regs short-lived)
    #define ISSUE_FILL(CH, BUFOFF)                                           \
    {                                                                        \
        const char* g = srcb + (size_t)(CH) * S3 * 4;                        \
        _Pragma("unroll")                                                    \
        for (int j = 0; j < SLOTS; j++) {                                    \
            if ((need >> j) & 1u) {                                          \
                int rowid = r0 + j * 128;                                    \
                int wz = rowid / WWN;                                        \
                int wy = rowid - wz * WWN;                                   \
                int gy = bay + wy, gz = baz + wz;                            \
                unsigned ok = (inb >> j) & 1u;                               \
                unsigned go = ok ? (unsigned)((((gz * SB) + gy) * SB + gxq) * 4) : 0u; \
                unsigned sz = ok << 4;                                       \
                asm volatile("cp.async.cg.shared.global [%0], [%1], 16, %2;" \
                    :: "r"(su + (BUFOFF) + sidx0 + (unsigned)(j * 16384)),   \
                       "l"(g + go), "r"(sz) : "memory");                     \
            }                                                                \
        }                                                                    \
        asm volatile("cp.async.commit_group;" ::: "memory");                 \
    }

    // prologue: fill channel 0 into buffer 0
    ISSUE_FILL(0, 0u);

    #pragma unroll 1
    for (int c = 0; c < CB; c++) {
        __syncthreads();             // gather(c-1) done: buf[(c+1)&1] free

        if (c + 1 < CB) {
            unsigned nxtoff = ((c + 1) & 1) ? (unsigned)WIN_BYTES : 0u;
            ISSUE_FILL(c + 1, nxtoff);
            asm volatile("cp.async.wait_group 1;" ::: "memory");  // fill(c) done
        } else {
            asm volatile("cp.async.wait_group 0;" ::: "memory");
        }
        __syncthreads();             // fill(c) visible to all warps

        const char* wb = wbase + ((c & 1) ? (unsigned)WIN_BYTES : 0u);
        char* dc = dstb + (size_t)c * S3 * 4 + obyte0;
        #pragma unroll
        for (int s = 0; s < SPT; s++) {
            unsigned rowid = (rpk[s >> 1] >> ((s & 1) * 16)) & 0xFFFFu;
            unsigned cap   = (capk[s >> 1] >> ((s & 1) * 16)) & 0xFFFFu;
            unsigned ca0 = cap & 0xFFu;
            unsigned ca1 = (cap >> 8) & 0xFFu;

            unsigned rk0 = rowid * 128 + ((rowid & 7) << 4);
            unsigned rr1 = rowid + 1;
            unsigned rk1 = rr1 * 128 + ((rr1 & 7) << 4);
            unsigned rr2 = rowid + WWN;
            unsigned rk2 = rr2 * 128 + ((rr2 & 7) << 4);
            unsigned rr3 = rowid + WWN + 1;
            unsigned rk3 = rr3 * 128 + ((rr3 & 7) << 4);

            float v00 = *(const float*)(wb + (rk0 ^ ca0));
            float v01 = *(const float*)(wb + (rk0 ^ ca1));
            float v10 = *(const float*)(wb + (rk1 ^ ca0));
            float v11 = *(const float*)(wb + (rk1 ^ ca1));
            float v20 = *(const float*)(wb + (rk2 ^ ca0));
            float v21 = *(const float*)(wb + (rk2 ^ ca1));
            float v30 = *(const float*)(wb + (rk3 ^ ca0));
            float v31 = *(const float*)(wb + (rk3 ^ ca1));

            float e0 = ex0[s], e1 = ex1[s];
            float s0 = fmaf(e0, v00, e1 * v01);
            float s1 = fmaf(e0, v10, e1 * v11);
            float s2 = fmaf(e0, v20, e1 * v21);
            float s3 = fmaf(e0, v30, e1 * v31);
            float acc = wp0[s] * s0;
            acc = fmaf(wp1[s], s1, acc);
            acc = fmaf(wp2[s], s2, acc);
            acc = fmaf(wp3[s], s3, acc);
            *(float*)(dc + (unsigned)(s * 65536)) = acc;   // lz += 4 per s
        }
    }
    #undef ISSUE_FILL
}

extern "C" void kernel_launch(void* const* d_in, const int* in_sizes, int n_in,
                              void* d_out, int out_size)
{
    const float* vol = (const float*)d_in[0];   // [8,16,64,64,64] f32
    const float* rot = (const float*)d_in[1];   // [8,3,3] f32
    float* out = (float*)d_out;

    cudaFuncSetAttribute(volrot_kernel,
                         cudaFuncAttributeMaxDynamicSharedMemorySize, SMEM_BYTES);

    volrot_kernel<<<8 * 64, NTHR, SMEM_BYTES>>>(vol, rot, out);
}